// round 11
// baseline (speedup 1.0000x reference)
#include <cuda_runtime.h>
#include <cstdint>
#include <math.h>

#define THREADS  256
#define PPB      64
#define NBLOCKS  4096

// ---- smem layout (32-bit words) ----
// xfr : fragment-major tf32 X: [koct(24)][mtile(4)][lane(32)][w(4)] = 12288 words
//       (overlaid after GEMM2 by stg[2][64][68] = 8704 words)
#define SM_B1S  12288
#define SM_W2S  (SM_B1S + 64)
#define SM_BFS  (SM_W2S + 64)
#define SM_SSP  (SM_BFS + 64)               // 2*6*64
#define SM_SS   (SM_SSP + 768)              // 6*64
#define SM_FLOATS (SM_SS + 384)
#define SM_BYTES (SM_FLOATS * 4)            // 54528 B -> 3 CTAs/SM

// weight fragment buffers in global scratch (L2-resident, written by prep kernel)
__device__ __align__(16) uint32_t g_w1_frag[8192];
__device__ __align__(16) uint32_t g_wf_frag[12288];

__device__ __forceinline__ uint32_t f2tf32(float v) {
    uint32_t o;
    asm("cvt.rna.tf32.f32 %0, %1;" : "=r"(o) : "f"(v));
    return o;
}
__device__ __forceinline__ void mma8(float d[4], const uint32_t a[4],
                                     uint32_t b0, uint32_t b1) {
    asm volatile(
        "mma.sync.aligned.m16n8k8.row.col.f32.tf32.tf32.f32 "
        "{%0,%1,%2,%3}, {%4,%5,%6,%7}, {%8,%9}, {%0,%1,%2,%3};"
        : "+f"(d[0]), "+f"(d[1]), "+f"(d[2]), "+f"(d[3])
        : "r"(a[0]), "r"(a[1]), "r"(a[2]), "r"(a[3]), "r"(b0), "r"(b1));
}
// gelu via Phi(h) ~= sigma(1.5976h + 0.07056h^3), |dPhi| <= ~1.4e-4
__device__ __forceinline__ float gelu_b(float h) {
    const float z = h * fmaf(h * h, 0.07056f, 1.5976f);
    return __fdividef(h, 1.0f + __expf(-z));
}

__global__ void __launch_bounds__(512)
prep_w(const float* __restrict__ W1, const float* __restrict__ Wf) {
    int i = blockIdx.x * 512 + threadIdx.x;
    if (i < 8192) {
        int r = i >> 6, e = i & 63;
        int n = (r < 64) ? e : (64 + e);
        int k = r & 63;
        int addr = ((k >> 3) * 16 + (n >> 3)) * 64 + ((n & 7) * 4 + (k & 3)) * 2 + ((k >> 2) & 1);
        g_w1_frag[addr] = f2tf32(W1[i]);
    } else if (i < 8192 + 12288) {
        int j = i - 8192;
        int r = j >> 6, c = j & 63;
        int addr = ((r >> 3) * 8 + (c >> 3)) * 64 + ((c & 7) * 4 + (r & 3)) * 2 + ((r >> 2) & 1);
        g_wf_frag[addr] = f2tf32(Wf[j]);
    }
}

__global__ void __launch_bounds__(THREADS, 3)
dig_mma9(const float* __restrict__ deg,
         const float* __restrict__ b1,
         const float* __restrict__ W2,
         const float* __restrict__ b2,
         const float* __restrict__ bf,
         float* __restrict__ out)
{
    extern __shared__ float sm[];
    uint32_t* xw  = (uint32_t*)sm;   // fragment-major tf32 X
    float*    stg = sm;              // overlaid after GEMM2: [2][64][68]
    float*    b1s = sm + SM_B1S;
    float*    w2s = sm + SM_W2S;
    float*    bfs = sm + SM_BFS;
    float*    ssp = sm + SM_SSP;     // [2][6][64]
    float*    ss  = sm + SM_SS;      // [6][64]

    const int tid  = threadIdx.x;
    const int wid  = tid >> 5;
    const int lane = tid & 31;
    const int g    = lane >> 2;
    const int tig  = lane & 3;
    const int m0   = (wid & 3) << 4;
    const int half = wid >> 2;

    const int bb  = blockIdx.x >> 10;
    const int hw0 = (blockIdx.x & 1023) << 6;

    // ------- stage X into fragment-major layout -------
    {
        const float* dptr = deg + (size_t)bb * 192 * 65536 + hw0;
        #pragma unroll
        for (int j = 0; j < 12; j++) {
            const int slot = j * THREADS + tid;
            const int koct = slot >> 7;
            const int mt   = (slot >> 5) & 3;
            const int ls   = slot & 31;
            const int p0 = (mt << 4) + (ls >> 2);
            const int c0 = (koct << 3) + (ls & 3);
            const float* q = dptr + (size_t)c0 * 65536 + p0;
            uint4 w;
            w.x = f2tf32(q[0]);
            w.y = f2tf32(q[8]);
            w.z = f2tf32(q[(size_t)4 * 65536]);
            w.w = f2tf32(q[(size_t)4 * 65536 + 8]);
            *(uint4*)(xw + slot * 4) = w;
        }
    }
    if (tid < 64) { b1s[tid] = b1[tid]; w2s[tid] = W2[tid]; bfs[tid] = bf[tid]; }
    __syncthreads();

    const uint32_t* xfr = xw + ((wid & 3) * 32 + lane) * 4;

    // -------- GEMM1 (tf32 MMA, B from L2) + in-register gating --------
    float sp[6][2] = {{0.f,0.f},{0.f,0.f},{0.f,0.f},{0.f,0.f},{0.f,0.f},{0.f,0.f}};
    const uint32_t* b1g = g_w1_frag + lane * 2;
    #pragma unroll
    for (int qq = 0; qq < 2; qq++) {
        const int qt = half * 2 + qq;
        float accA[3][2][4], accC[3][2][4];
        #pragma unroll
        for (int t = 0; t < 3; t++)
            #pragma unroll
            for (int n = 0; n < 2; n++)
                #pragma unroll
                for (int r = 0; r < 4; r++) { accA[t][n][r] = 0.f; accC[t][n][r] = 0.f; }

        #pragma unroll
        for (int k = 0; k < 8; k++) {
            uint32_t af[3][4];
            #pragma unroll
            for (int t = 0; t < 3; t++) {
                uint4 v = *(const uint4*)(xfr + (t * 8 + k) * 512);
                af[t][0] = v.x; af[t][1] = v.y; af[t][2] = v.z; af[t][3] = v.w;
            }
            #pragma unroll
            for (int nt = 0; nt < 2; nt++) {
                const int nb = qt * 2 + nt;
                uint2 av = __ldg((const uint2*)(b1g + (k * 16 + nb) * 64));
                #pragma unroll
                for (int t = 0; t < 3; t++) mma8(accA[t][nt], af[t], av.x, av.y);
                uint2 cv = __ldg((const uint2*)(b1g + (k * 16 + 8 + nb) * 64));
                #pragma unroll
                for (int t = 0; t < 3; t++) mma8(accC[t][nt], af[t], cv.x, cv.y);
            }
        }
        // gating partials
        #pragma unroll
        for (int nt = 0; nt < 2; nt++) {
            #pragma unroll
            for (int cc = 0; cc < 2; cc++) {
                const int e = qt * 16 + nt * 8 + 2 * tig + cc;
                const float bbv = b1s[e];
                const float wv  = w2s[e];
                #pragma unroll
                for (int r = 0; r < 2; r++) {
                    const int ri = 2 * r + cc;
                    sp[0][r] = fmaf(gelu_b(accA[0][nt][ri] + accC[1][nt][ri] + bbv), wv, sp[0][r]);
                    sp[1][r] = fmaf(gelu_b(accA[0][nt][ri] + accC[2][nt][ri] + bbv), wv, sp[1][r]);
                    sp[2][r] = fmaf(gelu_b(accA[1][nt][ri] + accC[0][nt][ri] + bbv), wv, sp[2][r]);
                    sp[3][r] = fmaf(gelu_b(accA[1][nt][ri] + accC[2][nt][ri] + bbv), wv, sp[3][r]);
                    sp[4][r] = fmaf(gelu_b(accA[2][nt][ri] + accC[0][nt][ri] + bbv), wv, sp[4][r]);
                    sp[5][r] = fmaf(gelu_b(accA[2][nt][ri] + accC[1][nt][ri] + bbv), wv, sp[5][r]);
                }
            }
        }
    }
    // 4-lane reduce, write per-half partials
    {
        #pragma unroll
        for (int q = 0; q < 6; q++) {
            #pragma unroll
            for (int r = 0; r < 2; r++) {
                float v = sp[q][r];
                v += __shfl_down_sync(0xffffffffu, v, 2, 4);
                v += __shfl_down_sync(0xffffffffu, v, 1, 4);
                if (tig == 0)
                    ssp[half * 384 + q * 64 + m0 + g + 8 * r] = v;
            }
        }
    }
    __syncthreads();
    {
        const float b2v = b2[0];
        #pragma unroll
        for (int i = tid; i < 384; i += THREADS)
            ss[i] = 1.0f / (1.0f + __expf(-(ssp[i] + ssp[384 + i] + b2v)));
    }
    __syncthreads();

    // -------- GEMM2 with fused Y-mix: D[64,64] = (M*X)[64,192] @ Wf --------
    float D[8][4];
    #pragma unroll
    for (int n = 0; n < 8; n++)
        #pragma unroll
        for (int r = 0; r < 4; r++) D[n][r] = 0.f;

    {
        const int p0 = m0 + g, p1 = p0 + 8;
        float mm[2][6];
        #pragma unroll
        for (int q = 0; q < 6; q++) { mm[0][q] = ss[q * 64 + p0]; mm[1][q] = ss[q * 64 + p1]; }

        const uint32_t* b2g = g_wf_frag + lane * 2;
        const int dd0 = half * 4;
        #pragma unroll
        for (int dd = dd0; dd < dd0 + 4; dd++) {
            float xf[3][4];
            #pragma unroll
            for (int t = 0; t < 3; t++) {
                uint4 v = *(const uint4*)(xfr + (t * 8 + dd) * 512);
                xf[t][0] = __uint_as_float(v.x);
                xf[t][1] = __uint_as_float(v.y);
                xf[t][2] = __uint_as_float(v.z);
                xf[t][3] = __uint_as_float(v.w);
            }
            #pragma unroll
            for (int t = 0; t < 3; t++) {
                const int u1 = (t == 0) ? 1 : 0;
                const int u2 = (t == 2) ? 1 : 2;
                uint32_t yf[4];
                #pragma unroll
                for (int r = 0; r < 4; r++) {
                    const int row = r & 1;   // w parity = pixel-row bit
                    float y = fmaf(mm[row][2 * t + 1], xf[u2][r],
                              fmaf(mm[row][2 * t],     xf[u1][r], xf[t][r]));
                    yf[r] = f2tf32(y);
                }
                const int kk = t * 8 + dd;
                #pragma unroll
                for (int n = 0; n < 8; n++) {
                    uint2 bv = __ldg((const uint2*)(b2g + (kk * 8 + n) * 64));
                    mma8(D[n], yf, bv.x, bv.y);
                }
            }
        }
    }
    __syncthreads();   // all xfr reads done; safe to overlay stg

    // -------- per-half partial staging (overlaid on xfr) --------
    {
        float* sh = stg + half * 4352;   // [64][68]
        #pragma unroll
        for (int n = 0; n < 8; n++) {
            #pragma unroll
            for (int cc = 0; cc < 2; cc++) {
                const int col = n * 8 + 2 * tig + cc;
                sh[col * 68 + m0 + g]     = D[n][cc];
                sh[col * 68 + m0 + g + 8] = D[n][2 + cc];
            }
        }
    }
    __syncthreads();

    // -------- combined epilogue: stg0 + stg1 + bf -> gmem (float4) --------
    {
        float* op = out + (size_t)bb * 64 * 65536 + hw0;
        #pragma unroll 4
        for (int i = tid; i < 64 * 16; i += THREADS) {
            int o = i >> 4, p4 = (i & 15) << 2;
            float4 v0 = *(const float4*)(stg + o * 68 + p4);
            float4 v1 = *(const float4*)(stg + 4352 + o * 68 + p4);
            const float bfv = bfs[o];
            float4 v;
            v.x = v0.x + v1.x + bfv;
            v.y = v0.y + v1.y + bfv;
            v.z = v0.z + v1.z + bfv;
            v.w = v0.w + v1.w + bfv;
            *(float4*)(op + (size_t)o * 65536 + p4) = v;
        }
    }
}

extern "C" void kernel_launch(void* const* d_in, const int* in_sizes, int n_in,
                              void* d_out, int out_size)
{
    const float* deg = (const float*)d_in[0];
    const float* W1  = (const float*)d_in[1];
    const float* b1  = (const float*)d_in[2];
    const float* W2  = (const float*)d_in[3];
    const float* b2  = (const float*)d_in[4];
    const float* Wf  = (const float*)d_in[5];
    const float* bf  = (const float*)d_in[6];
    float* outp = (float*)d_out;

    prep_w<<<40, 512>>>(W1, Wf);
    cudaFuncSetAttribute(dig_mma9, cudaFuncAttributeMaxDynamicSharedMemorySize, SM_BYTES);
    dig_mma9<<<NBLOCKS, THREADS, SM_BYTES>>>(deg, b1, W2, b2, bf, outp);
}

// round 12
// speedup vs baseline: 2.1703x; 2.1703x over previous
#include <cuda_runtime.h>
#include <cstdint>
#include <math.h>

#define THREADS  256
#define PPB      64
#define NBLOCKS  4096

// ---- smem layout (32-bit words) ----
// xfr : fragment-major tf32 X: [koct(24)][mtile(4)][lane(32)][w(4)] = 12288 words
//       (reused after GEMM2 as stg[2][64][68] = 8704 words)
// w1s : 8192 words, W1 fragments copied from global prep buffer
#define W1S_OFF 12288
#define SM_B1S  (W1S_OFF + 8192)            // 20480
#define SM_W2S  (SM_B1S + 64)
#define SM_BFS  (SM_W2S + 64)
#define SM_SSP  (SM_BFS + 64)               // 2*6*64
#define SM_SS   (SM_SSP + 768)              // 6*64
#define SM_FLOATS (SM_SS + 384)
#define SM_BYTES (SM_FLOATS * 4)            // 87296 B

// weight fragment buffers in global scratch (written by prep kernel)
__device__ __align__(16) uint32_t g_w1_frag[8192];
__device__ __align__(16) uint32_t g_wf_frag[12288];

__device__ __forceinline__ uint32_t f2tf32(float v) {
    uint32_t o;
    asm("cvt.rna.tf32.f32 %0, %1;" : "=r"(o) : "f"(v));
    return o;
}
__device__ __forceinline__ void mma8(float d[4], const uint32_t a[4],
                                     uint32_t b0, uint32_t b1) {
    asm volatile(
        "mma.sync.aligned.m16n8k8.row.col.f32.tf32.tf32.f32 "
        "{%0,%1,%2,%3}, {%4,%5,%6,%7}, {%8,%9}, {%0,%1,%2,%3};"
        : "+f"(d[0]), "+f"(d[1]), "+f"(d[2]), "+f"(d[3])
        : "r"(a[0]), "r"(a[1]), "r"(a[2]), "r"(a[3]), "r"(b0), "r"(b1));
}
__device__ __forceinline__ float tanh_f(float z) {
    float t;
    asm("tanh.approx.f32 %0, %1;" : "=f"(t) : "f"(z));
    return t;
}
// gelu: Phi(h) ~= sigma(1.5976h + 0.07056h^3) = 0.5(1 + tanh(0.7988h + 0.03528h^3))
__device__ __forceinline__ float gelu_t(float h) {
    const float z  = h * fmaf(h * h, 0.03528f, 0.7988f);
    const float hh = 0.5f * h;
    return fmaf(hh, tanh_f(z), hh);
}
__device__ __forceinline__ float sigmoid_t(float v) {
    return fmaf(0.5f, tanh_f(0.5f * v), 0.5f);
}

__global__ void __launch_bounds__(512)
prep_w(const float* __restrict__ W1, const float* __restrict__ Wf) {
    int i = blockIdx.x * 512 + threadIdx.x;
    if (i < 8192) {
        int r = i >> 6, e = i & 63;
        int n = (r < 64) ? e : (64 + e);
        int k = r & 63;
        int addr = ((k >> 3) * 16 + (n >> 3)) * 64 + ((n & 7) * 4 + (k & 3)) * 2 + ((k >> 2) & 1);
        g_w1_frag[addr] = f2tf32(W1[i]);
    } else if (i < 8192 + 12288) {
        int j = i - 8192;
        int r = j >> 6, c = j & 63;
        int addr = ((r >> 3) * 8 + (c >> 3)) * 64 + ((c & 7) * 4 + (r & 3)) * 2 + ((r >> 2) & 1);
        g_wf_frag[addr] = f2tf32(Wf[j]);
    }
}

__global__ void __launch_bounds__(THREADS, 2)
dig_mma10(const float* __restrict__ deg,
          const float* __restrict__ b1,
          const float* __restrict__ W2,
          const float* __restrict__ b2,
          const float* __restrict__ bf,
          float* __restrict__ out)
{
    extern __shared__ float sm[];
    uint32_t* xw  = (uint32_t*)sm;            // fragment-major tf32 X
    float*    stg = sm;                       // overlaid after GEMM2: [2][64][68]
    uint32_t* w1s = (uint32_t*)sm + W1S_OFF;
    float*    b1s = sm + SM_B1S;
    float*    w2s = sm + SM_W2S;
    float*    bfs = sm + SM_BFS;
    float*    ssp = sm + SM_SSP;     // [2][6][64]
    float*    ss  = sm + SM_SS;      // [6][64]

    const int tid  = threadIdx.x;
    const int wid  = tid >> 5;
    const int lane = tid & 31;
    const int g    = lane >> 2;
    const int tig  = lane & 3;
    const int m0   = (wid & 3) << 4;   // GEMM1 m-tile
    const int half = wid >> 2;         // GEMM1 e-half

    const int bb  = blockIdx.x >> 10;
    const int hw0 = (blockIdx.x & 1023) << 6;

    // ------- stage X into fragment-major layout -------
    {
        const float* dptr = deg + (size_t)bb * 192 * 65536 + hw0;
        #pragma unroll
        for (int j = 0; j < 12; j++) {
            const int slot = j * THREADS + tid;
            const int koct = slot >> 7;
            const int mt   = (slot >> 5) & 3;
            const int ls   = slot & 31;
            const int p0 = (mt << 4) + (ls >> 2);
            const int c0 = (koct << 3) + (ls & 3);
            const float* q = dptr + (size_t)c0 * 65536 + p0;
            uint4 w;
            w.x = f2tf32(q[0]);
            w.y = f2tf32(q[8]);
            w.z = f2tf32(q[(size_t)4 * 65536]);
            w.w = f2tf32(q[(size_t)4 * 65536 + 8]);
            *(uint4*)(xw + slot * 4) = w;
        }
    }
    // ------- copy W1 fragments into smem (coalesced uint4) -------
    #pragma unroll
    for (int i = tid; i < 2048; i += THREADS)
        ((uint4*)w1s)[i] = ((const uint4*)g_w1_frag)[i];
    if (tid < 64) { b1s[tid] = b1[tid]; w2s[tid] = W2[tid]; bfs[tid] = bf[tid]; }
    __syncthreads();

    const uint32_t* xfr = xw + ((wid & 3) * 32 + lane) * 4;

    // -------- GEMM1 (tf32 MMA, B from smem) + in-register gating --------
    float sp[6][2] = {{0.f,0.f},{0.f,0.f},{0.f,0.f},{0.f,0.f},{0.f,0.f},{0.f,0.f}};
    const uint32_t* b1p = w1s + lane * 2;
    #pragma unroll
    for (int qq = 0; qq < 2; qq++) {
        const int qt = half * 2 + qq;
        float accA[3][2][4], accC[3][2][4];
        #pragma unroll
        for (int t = 0; t < 3; t++)
            #pragma unroll
            for (int n = 0; n < 2; n++)
                #pragma unroll
                for (int r = 0; r < 4; r++) { accA[t][n][r] = 0.f; accC[t][n][r] = 0.f; }

        #pragma unroll
        for (int k = 0; k < 8; k++) {
            uint32_t af[3][4];
            #pragma unroll
            for (int t = 0; t < 3; t++) {
                uint4 v = *(const uint4*)(xfr + (t * 8 + k) * 512);
                af[t][0] = v.x; af[t][1] = v.y; af[t][2] = v.z; af[t][3] = v.w;
            }
            #pragma unroll
            for (int nt = 0; nt < 2; nt++) {
                const int nb = qt * 2 + nt;
                uint2 av = *(const uint2*)(b1p + (k * 16 + nb) * 64);
                #pragma unroll
                for (int t = 0; t < 3; t++) mma8(accA[t][nt], af[t], av.x, av.y);
                uint2 cv = *(const uint2*)(b1p + (k * 16 + 8 + nb) * 64);
                #pragma unroll
                for (int t = 0; t < 3; t++) mma8(accC[t][nt], af[t], cv.x, cv.y);
            }
        }
        // gating partials
        #pragma unroll
        for (int nt = 0; nt < 2; nt++) {
            #pragma unroll
            for (int cc = 0; cc < 2; cc++) {
                const int e = qt * 16 + nt * 8 + 2 * tig + cc;
                const float bbv = b1s[e];
                const float wv  = w2s[e];
                #pragma unroll
                for (int r = 0; r < 2; r++) {
                    const int ri = 2 * r + cc;
                    sp[0][r] = fmaf(gelu_t(accA[0][nt][ri] + accC[1][nt][ri] + bbv), wv, sp[0][r]);
                    sp[1][r] = fmaf(gelu_t(accA[0][nt][ri] + accC[2][nt][ri] + bbv), wv, sp[1][r]);
                    sp[2][r] = fmaf(gelu_t(accA[1][nt][ri] + accC[0][nt][ri] + bbv), wv, sp[2][r]);
                    sp[3][r] = fmaf(gelu_t(accA[1][nt][ri] + accC[2][nt][ri] + bbv), wv, sp[3][r]);
                    sp[4][r] = fmaf(gelu_t(accA[2][nt][ri] + accC[0][nt][ri] + bbv), wv, sp[4][r]);
                    sp[5][r] = fmaf(gelu_t(accA[2][nt][ri] + accC[1][nt][ri] + bbv), wv, sp[5][r]);
                }
            }
        }
    }
    // 4-lane reduce, write per-half partials
    {
        #pragma unroll
        for (int q = 0; q < 6; q++) {
            #pragma unroll
            for (int r = 0; r < 2; r++) {
                float v = sp[q][r];
                v += __shfl_down_sync(0xffffffffu, v, 2, 4);
                v += __shfl_down_sync(0xffffffffu, v, 1, 4);
                if (tig == 0)
                    ssp[half * 384 + q * 64 + m0 + g + 8 * r] = v;
            }
        }
    }
    __syncthreads();
    {
        const float b2v = b2[0];
        #pragma unroll
        for (int i = tid; i < 384; i += THREADS)
            ss[i] = sigmoid_t(ssp[i] + ssp[384 + i] + b2v);
    }
    __syncthreads();

    // -------- GEMM2 with fused Y-mix + m-pairing --------
    const int mp = wid & 1;
    const int kh = (wid >> 1) & 1;
    const int nh = wid >> 2;

    float D[2][4][4];
    #pragma unroll
    for (int mt = 0; mt < 2; mt++)
        #pragma unroll
        for (int n = 0; n < 4; n++)
            #pragma unroll
            for (int r = 0; r < 4; r++) D[mt][n][r] = 0.f;

    {
        float mm[2][2][6];   // [mt][row][pair]
        #pragma unroll
        for (int mt = 0; mt < 2; mt++) {
            const int p0 = (2 * mp + mt) * 16 + g;
            #pragma unroll
            for (int q = 0; q < 6; q++) {
                mm[mt][0][q] = ss[q * 64 + p0];
                mm[mt][1][q] = ss[q * 64 + p0 + 8];
            }
        }
        const uint32_t* b2g = g_wf_frag + lane * 2;
        const int dd0 = kh * 4;
        #pragma unroll
        for (int dd = dd0; dd < dd0 + 4; dd++) {
            uint32_t yfa[2][3][4];
            #pragma unroll
            for (int mt = 0; mt < 2; mt++) {
                const uint32_t* xm = xw + (((2 * mp + mt) * 32) + lane) * 4;
                float xf[3][4];
                #pragma unroll
                for (int t = 0; t < 3; t++) {
                    uint4 v = *(const uint4*)(xm + (t * 8 + dd) * 512);
                    xf[t][0] = __uint_as_float(v.x);
                    xf[t][1] = __uint_as_float(v.y);
                    xf[t][2] = __uint_as_float(v.z);
                    xf[t][3] = __uint_as_float(v.w);
                }
                #pragma unroll
                for (int t = 0; t < 3; t++) {
                    const int u1 = (t == 0) ? 1 : 0;
                    const int u2 = (t == 2) ? 1 : 2;
                    #pragma unroll
                    for (int r = 0; r < 4; r++) {
                        const int row = r & 1;
                        float y = fmaf(mm[mt][row][2 * t + 1], xf[u2][r],
                                  fmaf(mm[mt][row][2 * t],     xf[u1][r], xf[t][r]));
                        yfa[mt][t][r] = f2tf32(y);
                    }
                }
            }
            #pragma unroll
            for (int t = 0; t < 3; t++) {
                const int kk = t * 8 + dd;
                #pragma unroll
                for (int n = 0; n < 4; n++) {
                    uint2 bv = __ldg((const uint2*)(b2g + (kk * 8 + 4 * nh + n) * 64));
                    mma8(D[0][n], yfa[0][t], bv.x, bv.y);
                    mma8(D[1][n], yfa[1][t], bv.x, bv.y);
                }
            }
        }
    }
    __syncthreads();   // all xfr reads done; safe to overlay stg

    // -------- per-(kh) partial staging into overlaid stg --------
    {
        float* sh = stg + kh * 4352;   // [64][68]
        #pragma unroll
        for (int mt = 0; mt < 2; mt++) {
            const int row0 = (2 * mp + mt) * 16 + g;
            #pragma unroll
            for (int n = 0; n < 4; n++) {
                #pragma unroll
                for (int cc = 0; cc < 2; cc++) {
                    const int col = (4 * nh + n) * 8 + 2 * tig + cc;
                    sh[col * 68 + row0]     = D[mt][n][cc];
                    sh[col * 68 + row0 + 8] = D[mt][n][2 + cc];
                }
            }
        }
    }
    __syncthreads();

    // -------- combined epilogue: stg0 + stg1 + bf -> gmem (float4) --------
    {
        float* op = out + (size_t)bb * 64 * 65536 + hw0;
        #pragma unroll 4
        for (int i = tid; i < 64 * 16; i += THREADS) {
            int o = i >> 4, p4 = (i & 15) << 2;
            float4 v0 = *(const float4*)(stg + o * 68 + p4);
            float4 v1 = *(const float4*)(stg + 4352 + o * 68 + p4);
            const float bfv = bfs[o];
            float4 v;
            v.x = v0.x + v1.x + bfv;
            v.y = v0.y + v1.y + bfv;
            v.z = v0.z + v1.z + bfv;
            v.w = v0.w + v1.w + bfv;
            *(float4*)(op + (size_t)o * 65536 + p4) = v;
        }
    }
}

extern "C" void kernel_launch(void* const* d_in, const int* in_sizes, int n_in,
                              void* d_out, int out_size)
{
    const float* deg = (const float*)d_in[0];
    const float* W1  = (const float*)d_in[1];
    const float* b1  = (const float*)d_in[2];
    const float* W2  = (const float*)d_in[3];
    const float* b2  = (const float*)d_in[4];
    const float* Wf  = (const float*)d_in[5];
    const float* bf  = (const float*)d_in[6];
    float* outp = (float*)d_out;

    prep_w<<<40, 512>>>(W1, Wf);
    cudaFuncSetAttribute(dig_mma10, cudaFuncAttributeMaxDynamicSharedMemorySize, SM_BYTES);
    dig_mma10<<<NBLOCKS, THREADS, SM_BYTES>>>(deg, b1, W2, b2, bf, outp);
}

// round 13
// speedup vs baseline: 3.1706x; 1.4609x over previous
#include <cuda_runtime.h>
#include <cuda_fp16.h>
#include <cstdint>
#include <math.h>

#define THREADS  256
#define PPB      64
#define NBLOCKS  4096

// ---- smem layout (32-bit words) ----
// xh  : fp16 fragment-major X: [kc(12)][mt(4)][lane(32)][w(4)] = 6144 words (24KB)
// stg : [2][64][68] = 8704 words, OVERLAYS xh after GEMM2
#define SM_B1S  8704
#define SM_W2S  (SM_B1S + 64)
#define SM_BFS  (SM_W2S + 64)
#define SM_SSP  (SM_BFS + 64)               // 2*6*64
#define SM_SS   (SM_SSP + 768)              // 6*64
#define SM_FLOATS (SM_SS + 384)
#define SM_BYTES (SM_FLOATS * 4)            // 40192 B

// weight fragment buffers in global scratch (L1/L2-resident, written by prep)
__device__ __align__(16) uint32_t g_w1h[4096];    // W1 as fp16 B-fragments [kk(4)][ntile(16)][lane(32)][2]
__device__ __align__(16) uint32_t g_wf[12288];    // Wf as tf32 B-fragments, k-permuted [koct(24)][ntile(8)][lane(32)][2]

__device__ __forceinline__ uint32_t f2tf32(float v) {
    uint32_t o;
    asm("cvt.rna.tf32.f32 %0, %1;" : "=r"(o) : "f"(v));
    return o;
}
__device__ __forceinline__ uint32_t pack_h2(float lo, float hi) {
    __half2 h = __floats2half2_rn(lo, hi);
    return *reinterpret_cast<uint32_t*>(&h);
}
// tf32 m16n8k8
__device__ __forceinline__ void mma8(float d[4], const uint32_t a[4],
                                     uint32_t b0, uint32_t b1) {
    asm volatile(
        "mma.sync.aligned.m16n8k8.row.col.f32.tf32.tf32.f32 "
        "{%0,%1,%2,%3}, {%4,%5,%6,%7}, {%8,%9}, {%0,%1,%2,%3};"
        : "+f"(d[0]), "+f"(d[1]), "+f"(d[2]), "+f"(d[3])
        : "r"(a[0]), "r"(a[1]), "r"(a[2]), "r"(a[3]), "r"(b0), "r"(b1));
}
// fp16 m16n8k16 (fp32 accumulate)
__device__ __forceinline__ void mma16(float d[4], const uint32_t a[4],
                                      uint32_t b0, uint32_t b1) {
    asm volatile(
        "mma.sync.aligned.m16n8k16.row.col.f32.f16.f16.f32 "
        "{%0,%1,%2,%3}, {%4,%5,%6,%7}, {%8,%9}, {%0,%1,%2,%3};"
        : "+f"(d[0]), "+f"(d[1]), "+f"(d[2]), "+f"(d[3])
        : "r"(a[0]), "r"(a[1]), "r"(a[2]), "r"(a[3]), "r"(b0), "r"(b1));
}
__device__ __forceinline__ float tanh_f(float z) {
    float t;
    asm("tanh.approx.f32 %0, %1;" : "=f"(t) : "f"(z));
    return t;
}
// gelu: Phi(h) ~= 0.5(1 + tanh(0.7988h + 0.03528h^3))
__device__ __forceinline__ float gelu_t(float h) {
    const float z  = h * fmaf(h * h, 0.03528f, 0.7988f);
    const float hh = 0.5f * h;
    return fmaf(hh, tanh_f(z), hh);
}
__device__ __forceinline__ float sigmoid_t(float v) {
    return fmaf(0.5f, tanh_f(0.5f * v), 0.5f);
}

__global__ void __launch_bounds__(512)
prep_w(const float* __restrict__ W1, const float* __restrict__ Wf) {
    int i = blockIdx.x * 512 + threadIdx.x;
    if (i < 4096) {
        // W1 fp16 B-fragments: word (kk, ntile, lane, w)
        int w = i & 1, lane = (i >> 1) & 31, ntile = (i >> 6) & 15, kk = i >> 10;
        int g = lane >> 2, tig = lane & 3;
        int n = ntile * 8 + g;
        int k = kk * 16 + 2 * tig + 8 * w;
        int row = k + ((n >= 64) ? 64 : 0);
        int col = n & 63;
        g_w1h[i] = pack_h2(W1[row * 64 + col], W1[(row + 1) * 64 + col]);
    } else if (i < 4096 + 12288) {
        // Wf tf32 B-fragments with permuted k-slots: b0 <- k=2tig, b1 <- k=2tig+1
        int j = i - 4096;
        int w = j & 1, lane = (j >> 1) & 31, ntile = (j >> 6) & 7, koct = j >> 9;
        int g = lane >> 2, tig = lane & 3;
        int n = ntile * 8 + g;
        int k = koct * 8 + 2 * tig + w;
        g_wf[j] = f2tf32(Wf[k * 64 + n]);
    }
}

__global__ void __launch_bounds__(THREADS, 2)
dig_mma11(const float* __restrict__ deg,
          const float* __restrict__ b1,
          const float* __restrict__ W2,
          const float* __restrict__ b2,
          const float* __restrict__ bf,
          float* __restrict__ out)
{
    extern __shared__ float sm[];
    uint32_t* xh  = (uint32_t*)sm;   // fp16 fragment-major X
    float*    stg = sm;              // overlaid after GEMM2
    float*    b1s = sm + SM_B1S;
    float*    w2s = sm + SM_W2S;
    float*    bfs = sm + SM_BFS;
    float*    ssp = sm + SM_SSP;     // [2][6][64]
    float*    ss  = sm + SM_SS;      // [6][64]

    const int tid  = threadIdx.x;
    const int wid  = tid >> 5;
    const int lane = tid & 31;
    const int g    = lane >> 2;
    const int tig  = lane & 3;
    const int m0   = (wid & 3) << 4;   // GEMM1 m-tile
    const int half = wid >> 2;         // GEMM1 e-half

    const int bb  = blockIdx.x >> 10;
    const int hw0 = (blockIdx.x & 1023) << 6;

    // ------- stage X into fp16 fragment-major layout -------
    // word(kc, mt, lane, w): w0=(p0, c0:c0+1) w1=(p0+8, c0:c0+1) w2=(p0, c0+8:+9) w3=(p0+8, +8:+9)
    {
        const float* dptr = deg + (size_t)bb * 192 * 65536 + hw0;
        #pragma unroll
        for (int j = 0; j < 6; j++) {
            const int slot = j * THREADS + tid;          // 0..1535
            const int kc = slot >> 7;
            const int mt = (slot >> 5) & 3;
            const int ls = slot & 31;
            const int p0 = (mt << 4) + (ls >> 2);
            const int c0 = (kc << 4) + ((ls & 3) << 1);
            const float* q = dptr + (size_t)c0 * 65536 + p0;
            uint4 w;
            w.x = pack_h2(q[0],                    q[(size_t)65536]);
            w.y = pack_h2(q[8],                    q[(size_t)65536 + 8]);
            w.z = pack_h2(q[(size_t)8 * 65536],    q[(size_t)9 * 65536]);
            w.w = pack_h2(q[(size_t)8 * 65536 + 8],q[(size_t)9 * 65536 + 8]);
            *(uint4*)(xh + slot * 4) = w;
        }
    }
    if (tid < 64) { b1s[tid] = b1[tid]; w2s[tid] = W2[tid]; bfs[tid] = bf[tid]; }
    __syncthreads();

    const uint32_t* xfr = xh + ((wid & 3) * 32 + lane) * 4;   // kc stride = 512 words

    // -------- GEMM1 (fp16 m16n8k16 MMA, B from L1/L2) + in-register gating --------
    float sp[6][2] = {{0.f,0.f},{0.f,0.f},{0.f,0.f},{0.f,0.f},{0.f,0.f},{0.f,0.f}};
    #pragma unroll
    for (int qq = 0; qq < 2; qq++) {
        const int qt = half * 2 + qq;
        float accA[3][2][4], accC[3][2][4];
        #pragma unroll
        for (int t = 0; t < 3; t++)
            #pragma unroll
            for (int n = 0; n < 2; n++)
                #pragma unroll
                for (int r = 0; r < 4; r++) { accA[t][n][r] = 0.f; accC[t][n][r] = 0.f; }

        #pragma unroll
        for (int kk = 0; kk < 4; kk++) {
            uint32_t af[3][4];
            #pragma unroll
            for (int t = 0; t < 3; t++) {
                uint4 v = *(const uint4*)(xfr + (t * 4 + kk) * 512);
                af[t][0] = v.x; af[t][1] = v.y; af[t][2] = v.z; af[t][3] = v.w;
            }
            #pragma unroll
            for (int nt = 0; nt < 2; nt++) {
                const int ntA = qt * 2 + nt;
                uint2 av = __ldg((const uint2*)(g_w1h + ((kk * 16 + ntA) * 32 + lane) * 2));
                #pragma unroll
                for (int t = 0; t < 3; t++) mma16(accA[t][nt], af[t], av.x, av.y);
                const int ntC = 8 + qt * 2 + nt;
                uint2 cv = __ldg((const uint2*)(g_w1h + ((kk * 16 + ntC) * 32 + lane) * 2));
                #pragma unroll
                for (int t = 0; t < 3; t++) mma16(accC[t][nt], af[t], cv.x, cv.y);
            }
        }
        // gating partials
        #pragma unroll
        for (int nt = 0; nt < 2; nt++) {
            #pragma unroll
            for (int cc = 0; cc < 2; cc++) {
                const int e = qt * 16 + nt * 8 + 2 * tig + cc;
                const float bbv = b1s[e];
                const float wv  = w2s[e];
                #pragma unroll
                for (int r = 0; r < 2; r++) {
                    const int ri = 2 * r + cc;
                    sp[0][r] = fmaf(gelu_t(accA[0][nt][ri] + accC[1][nt][ri] + bbv), wv, sp[0][r]);
                    sp[1][r] = fmaf(gelu_t(accA[0][nt][ri] + accC[2][nt][ri] + bbv), wv, sp[1][r]);
                    sp[2][r] = fmaf(gelu_t(accA[1][nt][ri] + accC[0][nt][ri] + bbv), wv, sp[2][r]);
                    sp[3][r] = fmaf(gelu_t(accA[1][nt][ri] + accC[2][nt][ri] + bbv), wv, sp[3][r]);
                    sp[4][r] = fmaf(gelu_t(accA[2][nt][ri] + accC[0][nt][ri] + bbv), wv, sp[4][r]);
                    sp[5][r] = fmaf(gelu_t(accA[2][nt][ri] + accC[1][nt][ri] + bbv), wv, sp[5][r]);
                }
            }
        }
    }
    // 4-lane reduce, write per-half partials
    {
        #pragma unroll
        for (int q = 0; q < 6; q++) {
            #pragma unroll
            for (int r = 0; r < 2; r++) {
                float v = sp[q][r];
                v += __shfl_down_sync(0xffffffffu, v, 2, 4);
                v += __shfl_down_sync(0xffffffffu, v, 1, 4);
                if (tig == 0)
                    ssp[half * 384 + q * 64 + m0 + g + 8 * r] = v;
            }
        }
    }
    __syncthreads();
    {
        const float b2v = b2[0];
        #pragma unroll
        for (int i = tid; i < 384; i += THREADS)
            ss[i] = sigmoid_t(ssp[i] + ssp[384 + i] + b2v);
    }
    __syncthreads();

    // -------- GEMM2 (tf32, k-permuted fragments) with fused Y-mix + m-pairing --------
    const int mp = wid & 1;
    const int kh = (wid >> 1) & 1;
    const int nh = wid >> 2;

    float D[2][4][4];
    #pragma unroll
    for (int mt = 0; mt < 2; mt++)
        #pragma unroll
        for (int n = 0; n < 4; n++)
            #pragma unroll
            for (int r = 0; r < 4; r++) D[mt][n][r] = 0.f;

    {
        float mm[2][2][6];   // [mt][row][pair]
        #pragma unroll
        for (int mt = 0; mt < 2; mt++) {
            const int p0 = (2 * mp + mt) * 16 + g;
            #pragma unroll
            for (int q = 0; q < 6; q++) {
                mm[mt][0][q] = ss[q * 64 + p0];
                mm[mt][1][q] = ss[q * 64 + p0 + 8];
            }
        }
        const int dd0 = kh * 4;
        #pragma unroll
        for (int dd = dd0; dd < dd0 + 4; dd++) {
            const int sub = dd & 1;
            uint32_t yfa[2][3][4];
            #pragma unroll
            for (int mt = 0; mt < 2; mt++) {
                const int mtg = 2 * mp + mt;
                float xf[3][4];
                #pragma unroll
                for (int t = 0; t < 3; t++) {
                    const int kc = t * 4 + (dd >> 1);
                    uint2 v = *(const uint2*)(xh + ((kc * 4 + mtg) * 32 + lane) * 4 + 2 * sub);
                    float2 f0 = __half22float2(*reinterpret_cast<__half2*>(&v.x)); // row g:   (c, c+1)
                    float2 f1 = __half22float2(*reinterpret_cast<__half2*>(&v.y)); // row g+8: (c, c+1)
                    xf[t][0] = f0.x;  // k-slot tig   (channel c)
                    xf[t][1] = f1.x;
                    xf[t][2] = f0.y;  // k-slot tig+4 (channel c+1)
                    xf[t][3] = f1.y;
                }
                #pragma unroll
                for (int t = 0; t < 3; t++) {
                    const int u1 = (t == 0) ? 1 : 0;
                    const int u2 = (t == 2) ? 1 : 2;
                    #pragma unroll
                    for (int r = 0; r < 4; r++) {
                        const int row = r & 1;
                        float y = fmaf(mm[mt][row][2 * t + 1], xf[u2][r],
                                  fmaf(mm[mt][row][2 * t],     xf[u1][r], xf[t][r]));
                        yfa[mt][t][r] = f2tf32(y);
                    }
                }
            }
            #pragma unroll
            for (int t = 0; t < 3; t++) {
                const int kk = t * 8 + dd;   // k-octave in Wf
                #pragma unroll
                for (int n = 0; n < 4; n++) {
                    uint2 bv = __ldg((const uint2*)(g_wf + ((kk * 8 + 4 * nh + n) * 32 + lane) * 2));
                    mma8(D[0][n], yfa[0][t], bv.x, bv.y);
                    mma8(D[1][n], yfa[1][t], bv.x, bv.y);
                }
            }
        }
    }
    __syncthreads();   // all xh reads done; safe to overlay stg

    // -------- per-(kh) partial staging into overlaid stg --------
    {
        float* sh = stg + kh * 4352;   // [64][68]
        #pragma unroll
        for (int mt = 0; mt < 2; mt++) {
            const int row0 = (2 * mp + mt) * 16 + g;
            #pragma unroll
            for (int n = 0; n < 4; n++) {
                #pragma unroll
                for (int cc = 0; cc < 2; cc++) {
                    const int col = (4 * nh + n) * 8 + 2 * tig + cc;
                    sh[col * 68 + row0]     = D[mt][n][cc];
                    sh[col * 68 + row0 + 8] = D[mt][n][2 + cc];
                }
            }
        }
    }
    __syncthreads();

    // -------- combined epilogue: stg0 + stg1 + bf -> gmem (float4) --------
    {
        float* op = out + (size_t)bb * 64 * 65536 + hw0;
        #pragma unroll 4
        for (int i = tid; i < 64 * 16; i += THREADS) {
            int o = i >> 4, p4 = (i & 15) << 2;
            float4 v0 = *(const float4*)(stg + o * 68 + p4);
            float4 v1 = *(const float4*)(stg + 4352 + o * 68 + p4);
            const float bfv = bfs[o];
            float4 v;
            v.x = v0.x + v1.x + bfv;
            v.y = v0.y + v1.y + bfv;
            v.z = v0.z + v1.z + bfv;
            v.w = v0.w + v1.w + bfv;
            *(float4*)(op + (size_t)o * 65536 + p4) = v;
        }
    }
}

extern "C" void kernel_launch(void* const* d_in, const int* in_sizes, int n_in,
                              void* d_out, int out_size)
{
    const float* deg = (const float*)d_in[0];
    const float* W1  = (const float*)d_in[1];
    const float* b1  = (const float*)d_in[2];
    const float* W2  = (const float*)d_in[3];
    const float* b2  = (const float*)d_in[4];
    const float* Wf  = (const float*)d_in[5];
    const float* bf  = (const float*)d_in[6];
    float* outp = (float*)d_out;

    prep_w<<<32, 512>>>(W1, Wf);
    cudaFuncSetAttribute(dig_mma11, cudaFuncAttributeMaxDynamicSharedMemorySize, SM_BYTES);
    dig_mma11<<<NBLOCKS, THREADS, SM_BYTES>>>(deg, b1, W2, b2, bf, outp);
}

// round 14
// speedup vs baseline: 3.6092x; 1.1383x over previous
#include <cuda_runtime.h>
#include <cuda_fp16.h>
#include <cstdint>
#include <math.h>

#define THREADS  256
#define PPB      64
#define NBLOCKS  4096

// ---- smem layout (32-bit words) ----
// xh  : fp16 fragment-major X: [kc(12)][mt(4)][lane(32)][w(4)] = 6144 words (24KB)
// stg : [2][64][68] = 8704 words, OVERLAYS xh after GEMM2
#define SM_B1S  8704
#define SM_W2S  (SM_B1S + 64)
#define SM_BFS  (SM_W2S + 64)
#define SM_SSP  (SM_BFS + 64)               // 2*6*64
#define SM_SS   (SM_SSP + 768)              // 6*64
#define SM_FLOATS (SM_SS + 384)
#define SM_BYTES (SM_FLOATS * 4)            // 40192 B

// weight fragment buffers in global scratch (L1/L2-resident, written by prep)
__device__ __align__(16) uint32_t g_w1h[4096];   // W1 fp16 B-frags [kk(4)][ntile(16)][lane(32)][2]
__device__ __align__(16) uint32_t g_wfh[6144];   // Wf fp16 B-frags [kc(12)][ntile(8)][lane(32)][2]

__device__ __forceinline__ uint32_t pack_h2(float lo, float hi) {
    __half2 h = __floats2half2_rn(lo, hi);
    return *reinterpret_cast<uint32_t*>(&h);
}
// fp16 m16n8k16 (fp32 accumulate)
__device__ __forceinline__ void mma16(float d[4], const uint32_t a[4],
                                      uint32_t b0, uint32_t b1) {
    asm volatile(
        "mma.sync.aligned.m16n8k16.row.col.f32.f16.f16.f32 "
        "{%0,%1,%2,%3}, {%4,%5,%6,%7}, {%8,%9}, {%0,%1,%2,%3};"
        : "+f"(d[0]), "+f"(d[1]), "+f"(d[2]), "+f"(d[3])
        : "r"(a[0]), "r"(a[1]), "r"(a[2]), "r"(a[3]), "r"(b0), "r"(b1));
}
__device__ __forceinline__ float tanh_f(float z) {
    float t;
    asm("tanh.approx.f32 %0, %1;" : "=f"(t) : "f"(z));
    return t;
}
// gelu: Phi(h) ~= 0.5(1 + tanh(0.7988h + 0.03528h^3))
__device__ __forceinline__ float gelu_t(float h) {
    const float z  = h * fmaf(h * h, 0.03528f, 0.7988f);
    const float hh = 0.5f * h;
    return fmaf(hh, tanh_f(z), hh);
}
__device__ __forceinline__ float sigmoid_t(float v) {
    return fmaf(0.5f, tanh_f(0.5f * v), 0.5f);
}

__global__ void __launch_bounds__(512)
prep_w(const float* __restrict__ W1, const float* __restrict__ Wf) {
    int i = blockIdx.x * 512 + threadIdx.x;
    if (i < 4096) {
        // W1 fp16 B-fragments (GEMM1, k=64 per matrix half)
        int w = i & 1, lane = (i >> 1) & 31, ntile = (i >> 6) & 15, kk = i >> 10;
        int g = lane >> 2, tig = lane & 3;
        int n = ntile * 8 + g;
        int k = kk * 16 + 2 * tig + 8 * w;
        int row = k + ((n >= 64) ? 64 : 0);
        int col = n & 63;
        g_w1h[i] = pack_h2(W1[row * 64 + col], W1[(row + 1) * 64 + col]);
    } else if (i < 4096 + 6144) {
        // Wf fp16 B-fragments (GEMM2, k=192)
        int j = i - 4096;
        int w = j & 1, lane = (j >> 1) & 31, ntile = (j >> 6) & 7, kc = j >> 9;
        int g = lane >> 2, tig = lane & 3;
        int n = ntile * 8 + g;
        int k = kc * 16 + 2 * tig + 8 * w;
        g_wfh[j] = pack_h2(Wf[k * 64 + n], Wf[(k + 1) * 64 + n]);
    }
}

__global__ void __launch_bounds__(THREADS, 2)
dig_mma12(const float* __restrict__ deg,
          const float* __restrict__ b1,
          const float* __restrict__ W2,
          const float* __restrict__ b2,
          const float* __restrict__ bf,
          float* __restrict__ out)
{
    extern __shared__ float sm[];
    uint32_t* xh  = (uint32_t*)sm;   // fp16 fragment-major X
    float*    stg = sm;              // overlaid after GEMM2
    float*    b1s = sm + SM_B1S;
    float*    w2s = sm + SM_W2S;
    float*    bfs = sm + SM_BFS;
    float*    ssp = sm + SM_SSP;     // [2][6][64]
    float*    ss  = sm + SM_SS;      // [6][64]

    const int tid  = threadIdx.x;
    const int wid  = tid >> 5;
    const int lane = tid & 31;
    const int g    = lane >> 2;
    const int tig  = lane & 3;
    const int m0   = (wid & 3) << 4;   // GEMM1 m-tile
    const int half = wid >> 2;         // GEMM1 e-half

    const int bb  = blockIdx.x >> 10;
    const int hw0 = (blockIdx.x & 1023) << 6;

    // ------- stage X into fp16 fragment-major layout -------
    {
        const float* dptr = deg + (size_t)bb * 192 * 65536 + hw0;
        #pragma unroll
        for (int j = 0; j < 6; j++) {
            const int slot = j * THREADS + tid;          // 0..1535
            const int kc = slot >> 7;
            const int mt = (slot >> 5) & 3;
            const int ls = slot & 31;
            const int p0 = (mt << 4) + (ls >> 2);
            const int c0 = (kc << 4) + ((ls & 3) << 1);
            const float* q = dptr + (size_t)c0 * 65536 + p0;
            uint4 w;
            w.x = pack_h2(q[0],                    q[(size_t)65536]);
            w.y = pack_h2(q[8],                    q[(size_t)65536 + 8]);
            w.z = pack_h2(q[(size_t)8 * 65536],    q[(size_t)9 * 65536]);
            w.w = pack_h2(q[(size_t)8 * 65536 + 8],q[(size_t)9 * 65536 + 8]);
            *(uint4*)(xh + slot * 4) = w;
        }
    }
    if (tid < 64) { b1s[tid] = b1[tid]; w2s[tid] = W2[tid]; bfs[tid] = bf[tid]; }
    __syncthreads();

    const uint32_t* xfr = xh + ((wid & 3) * 32 + lane) * 4;   // kc stride = 512 words

    // -------- GEMM1 (fp16 m16n8k16 MMA) + in-register gating --------
    float sp[6][2] = {{0.f,0.f},{0.f,0.f},{0.f,0.f},{0.f,0.f},{0.f,0.f},{0.f,0.f}};
    #pragma unroll
    for (int qq = 0; qq < 2; qq++) {
        const int qt = half * 2 + qq;
        float accA[3][2][4], accC[3][2][4];
        #pragma unroll
        for (int t = 0; t < 3; t++)
            #pragma unroll
            for (int n = 0; n < 2; n++)
                #pragma unroll
                for (int r = 0; r < 4; r++) { accA[t][n][r] = 0.f; accC[t][n][r] = 0.f; }

        #pragma unroll
        for (int kk = 0; kk < 4; kk++) {
            uint32_t af[3][4];
            #pragma unroll
            for (int t = 0; t < 3; t++) {
                uint4 v = *(const uint4*)(xfr + (t * 4 + kk) * 512);
                af[t][0] = v.x; af[t][1] = v.y; af[t][2] = v.z; af[t][3] = v.w;
            }
            #pragma unroll
            for (int nt = 0; nt < 2; nt++) {
                const int ntA = qt * 2 + nt;
                uint2 av = __ldg((const uint2*)(g_w1h + ((kk * 16 + ntA) * 32 + lane) * 2));
                #pragma unroll
                for (int t = 0; t < 3; t++) mma16(accA[t][nt], af[t], av.x, av.y);
                const int ntC = 8 + qt * 2 + nt;
                uint2 cv = __ldg((const uint2*)(g_w1h + ((kk * 16 + ntC) * 32 + lane) * 2));
                #pragma unroll
                for (int t = 0; t < 3; t++) mma16(accC[t][nt], af[t], cv.x, cv.y);
            }
        }
        // gating partials
        #pragma unroll
        for (int nt = 0; nt < 2; nt++) {
            #pragma unroll
            for (int cc = 0; cc < 2; cc++) {
                const int e = qt * 16 + nt * 8 + 2 * tig + cc;
                const float bbv = b1s[e];
                const float wv  = w2s[e];
                #pragma unroll
                for (int r = 0; r < 2; r++) {
                    const int ri = 2 * r + cc;
                    sp[0][r] = fmaf(gelu_t(accA[0][nt][ri] + accC[1][nt][ri] + bbv), wv, sp[0][r]);
                    sp[1][r] = fmaf(gelu_t(accA[0][nt][ri] + accC[2][nt][ri] + bbv), wv, sp[1][r]);
                    sp[2][r] = fmaf(gelu_t(accA[1][nt][ri] + accC[0][nt][ri] + bbv), wv, sp[2][r]);
                    sp[3][r] = fmaf(gelu_t(accA[1][nt][ri] + accC[2][nt][ri] + bbv), wv, sp[3][r]);
                    sp[4][r] = fmaf(gelu_t(accA[2][nt][ri] + accC[0][nt][ri] + bbv), wv, sp[4][r]);
                    sp[5][r] = fmaf(gelu_t(accA[2][nt][ri] + accC[1][nt][ri] + bbv), wv, sp[5][r]);
                }
            }
        }
    }
    // 4-lane reduce, write per-half partials
    {
        #pragma unroll
        for (int q = 0; q < 6; q++) {
            #pragma unroll
            for (int r = 0; r < 2; r++) {
                float v = sp[q][r];
                v += __shfl_down_sync(0xffffffffu, v, 2, 4);
                v += __shfl_down_sync(0xffffffffu, v, 1, 4);
                if (tig == 0)
                    ssp[half * 384 + q * 64 + m0 + g + 8 * r] = v;
            }
        }
    }
    __syncthreads();
    {
        const float b2v = b2[0];
        #pragma unroll
        for (int i = tid; i < 384; i += THREADS)
            ss[i] = sigmoid_t(ssp[i] + ssp[384 + i] + b2v);
    }
    __syncthreads();

    // -------- GEMM2 (fp16 m16n8k16) with half2 fused Y-mix + m-pairing --------
    const int mp = wid & 1;
    const int kh = (wid >> 1) & 1;
    const int nh = wid >> 2;

    float D[2][4][4];
    #pragma unroll
    for (int mt = 0; mt < 2; mt++)
        #pragma unroll
        for (int n = 0; n < 4; n++)
            #pragma unroll
            for (int r = 0; r < 4; r++) D[mt][n][r] = 0.f;

    {
        // gate scalars as half2 broadcasts: [mt][row][pair]
        __half2 mh[2][2][6];
        #pragma unroll
        for (int mt = 0; mt < 2; mt++) {
            const int p0 = (2 * mp + mt) * 16 + g;
            #pragma unroll
            for (int q = 0; q < 6; q++) {
                mh[mt][0][q] = __float2half2_rn(ss[q * 64 + p0]);
                mh[mt][1][q] = __float2half2_rn(ss[q * 64 + p0 + 8]);
            }
        }
        // dd = k16-chunk within each t (0..3); warp kh handles 2 of them
        #pragma unroll
        for (int dd = kh * 2; dd < kh * 2 + 2; dd++) {
            uint32_t yfa[2][3][4];
            #pragma unroll
            for (int mt = 0; mt < 2; mt++) {
                const int mtg = 2 * mp + mt;
                __half2 xf[3][4];
                #pragma unroll
                for (int t = 0; t < 3; t++) {
                    uint4 v = *(const uint4*)(xh + (((t * 4 + dd) * 4 + mtg) * 32 + lane) * 4);
                    xf[t][0] = *reinterpret_cast<__half2*>(&v.x);
                    xf[t][1] = *reinterpret_cast<__half2*>(&v.y);
                    xf[t][2] = *reinterpret_cast<__half2*>(&v.z);
                    xf[t][3] = *reinterpret_cast<__half2*>(&v.w);
                }
                #pragma unroll
                for (int t = 0; t < 3; t++) {
                    const int u1 = (t == 0) ? 1 : 0;
                    const int u2 = (t == 2) ? 1 : 2;
                    #pragma unroll
                    for (int r = 0; r < 4; r++) {
                        const int row = r & 1;   // regs 0,2 -> row g ; 1,3 -> row g+8
                        __half2 y = __hfma2(mh[mt][row][2 * t + 1], xf[u2][r],
                                    __hfma2(mh[mt][row][2 * t],     xf[u1][r], xf[t][r]));
                        yfa[mt][t][r] = *reinterpret_cast<uint32_t*>(&y);
                    }
                }
            }
            #pragma unroll
            for (int t = 0; t < 3; t++) {
                const int kc = t * 4 + dd;   // k16-chunk in Wf
                #pragma unroll
                for (int n = 0; n < 4; n++) {
                    uint2 bv = __ldg((const uint2*)(g_wfh + ((kc * 8 + 4 * nh + n) * 32 + lane) * 2));
                    mma16(D[0][n], yfa[0][t], bv.x, bv.y);
                    mma16(D[1][n], yfa[1][t], bv.x, bv.y);
                }
            }
        }
    }
    __syncthreads();   // all xh reads done; safe to overlay stg

    // -------- per-(kh) partial staging into overlaid stg --------
    {
        float* sh = stg + kh * 4352;   // [64][68]
        #pragma unroll
        for (int mt = 0; mt < 2; mt++) {
            const int row0 = (2 * mp + mt) * 16 + g;
            #pragma unroll
            for (int n = 0; n < 4; n++) {
                #pragma unroll
                for (int cc = 0; cc < 2; cc++) {
                    const int col = (4 * nh + n) * 8 + 2 * tig + cc;
                    sh[col * 68 + row0]     = D[mt][n][cc];
                    sh[col * 68 + row0 + 8] = D[mt][n][2 + cc];
                }
            }
        }
    }
    __syncthreads();

    // -------- combined epilogue: stg0 + stg1 + bf -> gmem (float4) --------
    {
        float* op = out + (size_t)bb * 64 * 65536 + hw0;
        #pragma unroll 4
        for (int i = tid; i < 64 * 16; i += THREADS) {
            int o = i >> 4, p4 = (i & 15) << 2;
            float4 v0 = *(const float4*)(stg + o * 68 + p4);
            float4 v1 = *(const float4*)(stg + 4352 + o * 68 + p4);
            const float bfv = bfs[o];
            float4 v;
            v.x = v0.x + v1.x + bfv;
            v.y = v0.y + v1.y + bfv;
            v.z = v0.z + v1.z + bfv;
            v.w = v0.w + v1.w + bfv;
            *(float4*)(op + (size_t)o * 65536 + p4) = v;
        }
    }
}

extern "C" void kernel_launch(void* const* d_in, const int* in_sizes, int n_in,
                              void* d_out, int out_size)
{
    const float* deg = (const float*)d_in[0];
    const float* W1  = (const float*)d_in[1];
    const float* b1  = (const float*)d_in[2];
    const float* W2  = (const float*)d_in[3];
    const float* b2  = (const float*)d_in[4];
    const float* Wf  = (const float*)d_in[5];
    const float* bf  = (const float*)d_in[6];
    float* outp = (float*)d_out;

    prep_w<<<20, 512>>>(W1, Wf);
    cudaFuncSetAttribute(dig_mma12, cudaFuncAttributeMaxDynamicSharedMemorySize, SM_BYTES);
    dig_mma12<<<NBLOCKS, THREADS, SM_BYTES>>>(deg, b1, W2, b2, bf, outp);
}

// round 15
// speedup vs baseline: 4.0732x; 1.1286x over previous
#include <cuda_runtime.h>
#include <cuda_fp16.h>
#include <cstdint>
#include <math.h>

#define THREADS  256
#define PPB      64
#define NBLOCKS  4096

// ---- smem layout (32-bit words) ----
// xh  : fp16 fragment-major X: [kc(12)][mt(4)][lane(32)][w(4)] = 6144 words (24KB)
// stg : [2][64][68] = 8704 words, OVERLAYS xh after GEMM2
#define SM_B1H  8704                        // 32 words (b1 half2 pairs)
#define SM_W2H  (SM_B1H + 32)               // 32 words (W2 half2 pairs)
#define SM_BFS  (SM_W2H + 32)               // 64
#define SM_SSP  (SM_BFS + 64)               // 2*6*64
#define SM_SS   (SM_SSP + 768)              // 6*64
#define SM_FLOATS (SM_SS + 384)
#define SM_BYTES (SM_FLOATS * 4)

// weight fragment buffers in global scratch (L1/L2-resident, written by prep)
__device__ __align__(16) uint32_t g_w1h[4096];   // W1 fp16 B-frags [kk(4)][ntile(16)][lane(32)][2]
__device__ __align__(16) uint32_t g_wfh[6144];   // Wf fp16 B-frags [kc(12)][ntile(8)][lane(32)][2]

__device__ __forceinline__ uint32_t pack_h2(float lo, float hi) {
    __half2 h = __floats2half2_rn(lo, hi);
    return *reinterpret_cast<uint32_t*>(&h);
}
// fp16 m16n8k16, fp32 accumulate
__device__ __forceinline__ void mma16(float d[4], const uint32_t a[4],
                                      uint32_t b0, uint32_t b1) {
    asm volatile(
        "mma.sync.aligned.m16n8k16.row.col.f32.f16.f16.f32 "
        "{%0,%1,%2,%3}, {%4,%5,%6,%7}, {%8,%9}, {%0,%1,%2,%3};"
        : "+f"(d[0]), "+f"(d[1]), "+f"(d[2]), "+f"(d[3])
        : "r"(a[0]), "r"(a[1]), "r"(a[2]), "r"(a[3]), "r"(b0), "r"(b1));
}
// fp16 m16n8k16, fp16 accumulate (D/C packed half2: reg0=row g, reg1=row g+8)
__device__ __forceinline__ void mma16h(uint32_t d[2], const uint32_t a[4],
                                       uint32_t b0, uint32_t b1) {
    asm volatile(
        "mma.sync.aligned.m16n8k16.row.col.f16.f16.f16.f16 "
        "{%0,%1}, {%2,%3,%4,%5}, {%6,%7}, {%0,%1};"
        : "+r"(d[0]), "+r"(d[1])
        : "r"(a[0]), "r"(a[1]), "r"(a[2]), "r"(a[3]), "r"(b0), "r"(b1));
}
__device__ __forceinline__ float tanh_f(float z) {
    float t;
    asm("tanh.approx.f32 %0, %1;" : "=f"(t) : "f"(z));
    return t;
}
__device__ __forceinline__ uint32_t tanh_h2(uint32_t z) {
    uint32_t t;
    asm("tanh.approx.f16x2 %0, %1;" : "=r"(t) : "r"(z));
    return t;
}
__device__ __forceinline__ float sigmoid_t(float v) {
    return fmaf(0.5f, tanh_f(0.5f * v), 0.5f);
}
// packed gelu * w2, accumulated into sp (all half2):
// h -> 0.5h(1+tanh(0.7988h + 0.03528h^3)) * w2 + sp
__device__ __forceinline__ __half2 gelu_w2_h2(__half2 h, __half2 w2, __half2 sp) {
    const __half2 c3 = __float2half2_rn(0.03528f);
    const __half2 c1 = __float2half2_rn(0.7988f);
    const __half2 ch = __float2half2_rn(0.5f);
    __half2 z  = __hmul2(h, __hfma2(__hmul2(h, h), c3, c1));
    uint32_t zt = tanh_h2(*reinterpret_cast<uint32_t*>(&z));
    __half2 th = *reinterpret_cast<__half2*>(&zt);
    __half2 hh = __hmul2(h, ch);
    __half2 gl = __hfma2(hh, th, hh);
    return __hfma2(gl, w2, sp);
}

__global__ void __launch_bounds__(512)
prep_w(const float* __restrict__ W1, const float* __restrict__ Wf) {
    int i = blockIdx.x * 512 + threadIdx.x;
    if (i < 4096) {
        int w = i & 1, lane = (i >> 1) & 31, ntile = (i >> 6) & 15, kk = i >> 10;
        int g = lane >> 2, tig = lane & 3;
        int n = ntile * 8 + g;
        int k = kk * 16 + 2 * tig + 8 * w;
        int row = k + ((n >= 64) ? 64 : 0);
        int col = n & 63;
        g_w1h[i] = pack_h2(W1[row * 64 + col], W1[(row + 1) * 64 + col]);
    } else if (i < 4096 + 6144) {
        int j = i - 4096;
        int w = j & 1, lane = (j >> 1) & 31, ntile = (j >> 6) & 7, kc = j >> 9;
        int g = lane >> 2, tig = lane & 3;
        int n = ntile * 8 + g;
        int k = kc * 16 + 2 * tig + 8 * w;
        g_wfh[j] = pack_h2(Wf[k * 64 + n], Wf[(k + 1) * 64 + n]);
    }
}

__global__ void __launch_bounds__(THREADS, 2)
dig_mma13(const float* __restrict__ deg,
          const float* __restrict__ b1,
          const float* __restrict__ W2,
          const float* __restrict__ b2,
          const float* __restrict__ bf,
          float* __restrict__ out)
{
    extern __shared__ float sm[];
    uint32_t* xh  = (uint32_t*)sm;   // fp16 fragment-major X
    float*    stg = sm;              // overlaid after GEMM2
    uint32_t* b1h = (uint32_t*)sm + SM_B1H;   // half2 pairs of b1
    uint32_t* w2h = (uint32_t*)sm + SM_W2H;   // half2 pairs of W2
    float*    bfs = sm + SM_BFS;
    float*    ssp = sm + SM_SSP;     // [2][6][64]
    float*    ss  = sm + SM_SS;      // [6][64]

    const int tid  = threadIdx.x;
    const int wid  = tid >> 5;
    const int lane = tid & 31;
    const int g    = lane >> 2;
    const int tig  = lane & 3;
    const int m0   = (wid & 3) << 4;   // GEMM1 m-tile
    const int half = wid >> 2;         // GEMM1 e-half

    const int bb  = blockIdx.x >> 10;
    const int hw0 = (blockIdx.x & 1023) << 6;

    // ------- stage X into fp16 fragment-major layout -------
    {
        const float* dptr = deg + (size_t)bb * 192 * 65536 + hw0;
        #pragma unroll
        for (int j = 0; j < 6; j++) {
            const int slot = j * THREADS + tid;          // 0..1535
            const int kc = slot >> 7;
            const int mt = (slot >> 5) & 3;
            const int ls = slot & 31;
            const int p0 = (mt << 4) + (ls >> 2);
            const int c0 = (kc << 4) + ((ls & 3) << 1);
            const float* q = dptr + (size_t)c0 * 65536 + p0;
            uint4 w;
            w.x = pack_h2(q[0],                    q[(size_t)65536]);
            w.y = pack_h2(q[8],                    q[(size_t)65536 + 8]);
            w.z = pack_h2(q[(size_t)8 * 65536],    q[(size_t)9 * 65536]);
            w.w = pack_h2(q[(size_t)8 * 65536 + 8],q[(size_t)9 * 65536 + 8]);
            *(uint4*)(xh + slot * 4) = w;
        }
    }
    if (tid < 32) {
        b1h[tid] = pack_h2(b1[2 * tid], b1[2 * tid + 1]);
        w2h[tid] = pack_h2(W2[2 * tid], W2[2 * tid + 1]);
    }
    if (tid < 64) bfs[tid] = bf[tid];
    __syncthreads();

    const uint32_t* xfr = xh + ((wid & 3) * 32 + lane) * 4;   // kc stride = 512 words

    // -------- GEMM1 (fp16 MMA, fp16 accumulators) + half2 gating --------
    float spf[6][2] = {{0.f,0.f},{0.f,0.f},{0.f,0.f},{0.f,0.f},{0.f,0.f},{0.f,0.f}};
    #pragma unroll
    for (int qq = 0; qq < 2; qq++) {
        const int qt = half * 2 + qq;
        uint32_t accA[3][2][2], accC[3][2][2];
        #pragma unroll
        for (int t = 0; t < 3; t++)
            #pragma unroll
            for (int nt = 0; nt < 2; nt++) {
                const uint32_t bb1 = b1h[qt * 8 + nt * 4 + tig];  // (b1[e], b1[e+1])
                accA[t][nt][0] = 0u; accA[t][nt][1] = 0u;
                accC[t][nt][0] = bb1; accC[t][nt][1] = bb1;       // fold +b1 into init
            }

        #pragma unroll
        for (int kk = 0; kk < 4; kk++) {
            uint32_t af[3][4];
            #pragma unroll
            for (int t = 0; t < 3; t++) {
                uint4 v = *(const uint4*)(xfr + (t * 4 + kk) * 512);
                af[t][0] = v.x; af[t][1] = v.y; af[t][2] = v.z; af[t][3] = v.w;
            }
            #pragma unroll
            for (int nt = 0; nt < 2; nt++) {
                const int ntA = qt * 2 + nt;
                uint2 av = __ldg((const uint2*)(g_w1h + ((kk * 16 + ntA) * 32 + lane) * 2));
                #pragma unroll
                for (int t = 0; t < 3; t++) mma16h(accA[t][nt], af[t], av.x, av.y);
                const int ntC = 8 + qt * 2 + nt;
                uint2 cv = __ldg((const uint2*)(g_w1h + ((kk * 16 + ntC) * 32 + lane) * 2));
                #pragma unroll
                for (int t = 0; t < 3; t++) mma16h(accC[t][nt], af[t], cv.x, cv.y);
            }
        }
        // half2 gating: per (nt, row): 6 pair gelus in packed fp16
        __half2 sph[6][2];
        #pragma unroll
        for (int q = 0; q < 6; q++)
            #pragma unroll
            for (int r = 0; r < 2; r++) sph[q][r] = __float2half2_rn(0.f);

        #pragma unroll
        for (int nt = 0; nt < 2; nt++) {
            const uint32_t w2u = w2h[qt * 8 + nt * 4 + tig];
            const __half2 wv = *reinterpret_cast<const __half2*>(&w2u);
            #pragma unroll
            for (int r = 0; r < 2; r++) {
                __half2 A0 = *reinterpret_cast<__half2*>(&accA[0][nt][r]);
                __half2 A1 = *reinterpret_cast<__half2*>(&accA[1][nt][r]);
                __half2 A2 = *reinterpret_cast<__half2*>(&accA[2][nt][r]);
                __half2 C0 = *reinterpret_cast<__half2*>(&accC[0][nt][r]);
                __half2 C1 = *reinterpret_cast<__half2*>(&accC[1][nt][r]);
                __half2 C2 = *reinterpret_cast<__half2*>(&accC[2][nt][r]);
                sph[0][r] = gelu_w2_h2(__hadd2(A0, C1), wv, sph[0][r]);
                sph[1][r] = gelu_w2_h2(__hadd2(A0, C2), wv, sph[1][r]);
                sph[2][r] = gelu_w2_h2(__hadd2(A1, C0), wv, sph[2][r]);
                sph[3][r] = gelu_w2_h2(__hadd2(A1, C2), wv, sph[3][r]);
                sph[4][r] = gelu_w2_h2(__hadd2(A2, C0), wv, sph[4][r]);
                sph[5][r] = gelu_w2_h2(__hadd2(A2, C1), wv, sph[5][r]);
            }
        }
        // unpack half2 partials -> fp32
        #pragma unroll
        for (int q = 0; q < 6; q++)
            #pragma unroll
            for (int r = 0; r < 2; r++) {
                float2 f = __half22float2(sph[q][r]);
                spf[q][r] += f.x + f.y;
            }
    }
    // 4-lane reduce, write per-half partials
    {
        #pragma unroll
        for (int q = 0; q < 6; q++) {
            #pragma unroll
            for (int r = 0; r < 2; r++) {
                float v = spf[q][r];
                v += __shfl_down_sync(0xffffffffu, v, 2, 4);
                v += __shfl_down_sync(0xffffffffu, v, 1, 4);
                if (tig == 0)
                    ssp[half * 384 + q * 64 + m0 + g + 8 * r] = v;
            }
        }
    }
    __syncthreads();
    {
        const float b2v = b2[0];
        #pragma unroll
        for (int i = tid; i < 384; i += THREADS)
            ss[i] = sigmoid_t(ssp[i] + ssp[384 + i] + b2v);
    }
    __syncthreads();

    // -------- GEMM2 (fp16 m16n8k16, fp32 accum) with half2 fused Y-mix --------
    const int mp = wid & 1;
    const int kh = (wid >> 1) & 1;
    const int nh = wid >> 2;

    float D[2][4][4];
    #pragma unroll
    for (int mt = 0; mt < 2; mt++)
        #pragma unroll
        for (int n = 0; n < 4; n++)
            #pragma unroll
            for (int r = 0; r < 4; r++) D[mt][n][r] = 0.f;

    {
        __half2 mh[2][2][6];
        #pragma unroll
        for (int mt = 0; mt < 2; mt++) {
            const int p0 = (2 * mp + mt) * 16 + g;
            #pragma unroll
            for (int q = 0; q < 6; q++) {
                mh[mt][0][q] = __float2half2_rn(ss[q * 64 + p0]);
                mh[mt][1][q] = __float2half2_rn(ss[q * 64 + p0 + 8]);
            }
        }
        #pragma unroll
        for (int dd = kh * 2; dd < kh * 2 + 2; dd++) {
            uint32_t yfa[2][3][4];
            #pragma unroll
            for (int mt = 0; mt < 2; mt++) {
                const int mtg = 2 * mp + mt;
                __half2 xf[3][4];
                #pragma unroll
                for (int t = 0; t < 3; t++) {
                    uint4 v = *(const uint4*)(xh + (((t * 4 + dd) * 4 + mtg) * 32 + lane) * 4);
                    xf[t][0] = *reinterpret_cast<__half2*>(&v.x);
                    xf[t][1] = *reinterpret_cast<__half2*>(&v.y);
                    xf[t][2] = *reinterpret_cast<__half2*>(&v.z);
                    xf[t][3] = *reinterpret_cast<__half2*>(&v.w);
                }
                #pragma unroll
                for (int t = 0; t < 3; t++) {
                    const int u1 = (t == 0) ? 1 : 0;
                    const int u2 = (t == 2) ? 1 : 2;
                    #pragma unroll
                    for (int r = 0; r < 4; r++) {
                        const int row = r & 1;
                        __half2 y = __hfma2(mh[mt][row][2 * t + 1], xf[u2][r],
                                    __hfma2(mh[mt][row][2 * t],     xf[u1][r], xf[t][r]));
                        yfa[mt][t][r] = *reinterpret_cast<uint32_t*>(&y);
                    }
                }
            }
            #pragma unroll
            for (int t = 0; t < 3; t++) {
                const int kc = t * 4 + dd;
                #pragma unroll
                for (int n = 0; n < 4; n++) {
                    uint2 bv = __ldg((const uint2*)(g_wfh + ((kc * 8 + 4 * nh + n) * 32 + lane) * 2));
                    mma16(D[0][n], yfa[0][t], bv.x, bv.y);
                    mma16(D[1][n], yfa[1][t], bv.x, bv.y);
                }
            }
        }
    }
    __syncthreads();   // all xh reads done; safe to overlay stg

    // -------- per-(kh) partial staging into overlaid stg --------
    {
        float* sh = stg + kh * 4352;   // [64][68]
        #pragma unroll
        for (int mt = 0; mt < 2; mt++) {
            const int row0 = (2 * mp + mt) * 16 + g;
            #pragma unroll
            for (int n = 0; n < 4; n++) {
                #pragma unroll
                for (int cc = 0; cc < 2; cc++) {
                    const int col = (4 * nh + n) * 8 + 2 * tig + cc;
                    sh[col * 68 + row0]     = D[mt][n][cc];
                    sh[col * 68 + row0 + 8] = D[mt][n][2 + cc];
                }
            }
        }
    }
    __syncthreads();

    // -------- combined epilogue: stg0 + stg1 + bf -> gmem (float4) --------
    {
        float* op = out + (size_t)bb * 64 * 65536 + hw0;
        #pragma unroll 4
        for (int i = tid; i < 64 * 16; i += THREADS) {
            int o = i >> 4, p4 = (i & 15) << 2;
            float4 v0 = *(const float4*)(stg + o * 68 + p4);
            float4 v1 = *(const float4*)(stg + 4352 + o * 68 + p4);
            const float bfv = bfs[o];
            float4 v;
            v.x = v0.x + v1.x + bfv;
            v.y = v0.y + v1.y + bfv;
            v.z = v0.z + v1.z + bfv;
            v.w = v0.w + v1.w + bfv;
            *(float4*)(op + (size_t)o * 65536 + p4) = v;
        }
    }
}

extern "C" void kernel_launch(void* const* d_in, const int* in_sizes, int n_in,
                              void* d_out, int out_size)
{
    const float* deg = (const float*)d_in[0];
    const float* W1  = (const float*)d_in[1];
    const float* b1  = (const float*)d_in[2];
    const float* W2  = (const float*)d_in[3];
    const float* b2  = (const float*)d_in[4];
    const float* Wf  = (const float*)d_in[5];
    const float* bf  = (const float*)d_in[6];
    float* outp = (float*)d_out;

    prep_w<<<20, 512>>>(W1, Wf);
    cudaFuncSetAttribute(dig_mma13, cudaFuncAttributeMaxDynamicSharedMemorySize, SM_BYTES);
    dig_mma13<<<NBLOCKS, THREADS, SM_BYTES>>>(deg, b1, W2, b2, bf, outp);
}

// round 16
// speedup vs baseline: 4.2913x; 1.0535x over previous
#include <cuda_runtime.h>
#include <cuda_fp16.h>
#include <cstdint>
#include <math.h>

#define THREADS  256
#define PPB      128
#define NBLOCKS  2048

// ---- smem layout (32-bit words) ----
// xh  : fp16 fragment-major X: [kc(12)][mt(8)][lane(32)][w(4)] = 12288 words (48KB)
//       (stg[64][132] = 8448 words overlays xh after GEMM2)
#define SM_B1H  12288
#define SM_W2H  (SM_B1H + 32)
#define SM_BFS  (SM_W2H + 32)
#define SM_WORDS (SM_BFS + 64)
#define SM_BYTES (SM_WORDS * 4)             // 49664 B -> 2 CTAs/SM

// weight fragment buffers in global scratch (L1/L2-resident, written by prep)
__device__ __align__(16) uint32_t g_w1h[4096];   // W1 fp16 B-frags [kk(4)][ntile(16)][lane(32)][2]
__device__ __align__(16) uint32_t g_wfh[6144];   // Wf fp16 B-frags [kc(12)][ntile(8)][lane(32)][2]

__device__ __forceinline__ uint32_t pack_h2(float lo, float hi) {
    __half2 h = __floats2half2_rn(lo, hi);
    return *reinterpret_cast<uint32_t*>(&h);
}
// fp16 m16n8k16, fp32 accumulate
__device__ __forceinline__ void mma16(float d[4], const uint32_t a[4],
                                      uint32_t b0, uint32_t b1) {
    asm volatile(
        "mma.sync.aligned.m16n8k16.row.col.f32.f16.f16.f32 "
        "{%0,%1,%2,%3}, {%4,%5,%6,%7}, {%8,%9}, {%0,%1,%2,%3};"
        : "+f"(d[0]), "+f"(d[1]), "+f"(d[2]), "+f"(d[3])
        : "r"(a[0]), "r"(a[1]), "r"(a[2]), "r"(a[3]), "r"(b0), "r"(b1));
}
// fp16 m16n8k16, fp16 accumulate (packed half2: reg0=row g, reg1=row g+8)
__device__ __forceinline__ void mma16h(uint32_t d[2], const uint32_t a[4],
                                       uint32_t b0, uint32_t b1) {
    asm volatile(
        "mma.sync.aligned.m16n8k16.row.col.f16.f16.f16.f16 "
        "{%0,%1}, {%2,%3,%4,%5}, {%6,%7}, {%0,%1};"
        : "+r"(d[0]), "+r"(d[1])
        : "r"(a[0]), "r"(a[1]), "r"(a[2]), "r"(a[3]), "r"(b0), "r"(b1));
}
__device__ __forceinline__ float tanh_f(float z) {
    float t;
    asm("tanh.approx.f32 %0, %1;" : "=f"(t) : "f"(z));
    return t;
}
__device__ __forceinline__ uint32_t tanh_h2(uint32_t z) {
    uint32_t t;
    asm("tanh.approx.f16x2 %0, %1;" : "=r"(t) : "r"(z));
    return t;
}
__device__ __forceinline__ float sigmoid_t(float v) {
    return fmaf(0.5f, tanh_f(0.5f * v), 0.5f);
}
// packed gelu(h) * w2 + sp
__device__ __forceinline__ __half2 gelu_w2_h2(__half2 h, __half2 w2, __half2 sp) {
    const __half2 c3 = __float2half2_rn(0.03528f);
    const __half2 c1 = __float2half2_rn(0.7988f);
    const __half2 ch = __float2half2_rn(0.5f);
    __half2 z  = __hmul2(h, __hfma2(__hmul2(h, h), c3, c1));
    uint32_t zt = tanh_h2(*reinterpret_cast<uint32_t*>(&z));
    __half2 th = *reinterpret_cast<__half2*>(&zt);
    __half2 hh = __hmul2(h, ch);
    __half2 gl = __hfma2(hh, th, hh);
    return __hfma2(gl, w2, sp);
}

__global__ void __launch_bounds__(512)
prep_w(const float* __restrict__ W1, const float* __restrict__ Wf) {
    int i = blockIdx.x * 512 + threadIdx.x;
    if (i < 4096) {
        int w = i & 1, lane = (i >> 1) & 31, ntile = (i >> 6) & 15, kk = i >> 10;
        int g = lane >> 2, tig = lane & 3;
        int n = ntile * 8 + g;
        int k = kk * 16 + 2 * tig + 8 * w;
        int row = k + ((n >= 64) ? 64 : 0);
        int col = n & 63;
        g_w1h[i] = pack_h2(W1[row * 64 + col], W1[(row + 1) * 64 + col]);
    } else if (i < 4096 + 6144) {
        int j = i - 4096;
        int w = j & 1, lane = (j >> 1) & 31, ntile = (j >> 6) & 7, kc = j >> 9;
        int g = lane >> 2, tig = lane & 3;
        int n = ntile * 8 + g;
        int k = kc * 16 + 2 * tig + 8 * w;
        g_wfh[j] = pack_h2(Wf[k * 64 + n], Wf[(k + 1) * 64 + n]);
    }
}

__global__ void __launch_bounds__(THREADS, 2)
dig_mma14(const float* __restrict__ deg,
          const float* __restrict__ b1,
          const float* __restrict__ W2,
          const float* __restrict__ b2,
          const float* __restrict__ bf,
          float* __restrict__ out)
{
    extern __shared__ float sm[];
    uint32_t* xh  = (uint32_t*)sm;   // fp16 fragment-major X
    float*    stg = sm;              // overlaid after GEMM2: [64][132]
    uint32_t* b1h = (uint32_t*)sm + SM_B1H;
    uint32_t* w2h = (uint32_t*)sm + SM_W2H;
    float*    bfs = sm + SM_BFS;

    const int tid  = threadIdx.x;
    const int wid  = tid >> 5;
    const int lane = tid & 31;
    const int g    = lane >> 2;
    const int tig  = lane & 3;
    const int m0   = wid << 4;       // each warp owns 16 pixels

    const int bb  = blockIdx.x >> 9;
    const int hw0 = (blockIdx.x & 511) << 7;

    // ------- stage X into fp16 fragment-major layout -------
    {
        const float* dptr = deg + (size_t)bb * 192 * 65536 + hw0;
        #pragma unroll
        for (int j = 0; j < 12; j++) {
            const int slot = j * THREADS + tid;          // 0..3071
            const int kc = slot >> 8;
            const int mt = (slot >> 5) & 7;
            const int ls = slot & 31;
            const int p0 = (mt << 4) + (ls >> 2);
            const int c0 = (kc << 4) + ((ls & 3) << 1);
            const float* q = dptr + (size_t)c0 * 65536 + p0;
            uint4 w;
            w.x = pack_h2(q[0],                    q[(size_t)65536]);
            w.y = pack_h2(q[8],                    q[(size_t)65536 + 8]);
            w.z = pack_h2(q[(size_t)8 * 65536],    q[(size_t)9 * 65536]);
            w.w = pack_h2(q[(size_t)8 * 65536 + 8],q[(size_t)9 * 65536 + 8]);
            *(uint4*)(xh + slot * 4) = w;
        }
    }
    if (tid < 32) {
        b1h[tid] = pack_h2(b1[2 * tid], b1[2 * tid + 1]);
        w2h[tid] = pack_h2(W2[2 * tid], W2[2 * tid + 1]);
    }
    if (tid < 64) bfs[tid] = bf[tid];
    __syncthreads();

    const uint32_t* xfr = xh + ((wid << 5) + lane) * 4;   // kc stride = 1024 words

    // -------- GEMM1 (fp16 MMA, fp16 acc) + half2 gating: full e per warp --------
    float spf[6][2] = {{0.f,0.f},{0.f,0.f},{0.f,0.f},{0.f,0.f},{0.f,0.f},{0.f,0.f}};
    #pragma unroll
    for (int qt = 0; qt < 4; qt++) {
        uint32_t accA[3][2][2], accC[3][2][2];
        #pragma unroll
        for (int t = 0; t < 3; t++)
            #pragma unroll
            for (int nt = 0; nt < 2; nt++) {
                const uint32_t bb1 = b1h[qt * 8 + nt * 4 + tig];
                accA[t][nt][0] = 0u;  accA[t][nt][1] = 0u;
                accC[t][nt][0] = bb1; accC[t][nt][1] = bb1;   // fold +b1
            }

        #pragma unroll
        for (int kk = 0; kk < 4; kk++) {
            uint32_t af[3][4];
            #pragma unroll
            for (int t = 0; t < 3; t++) {
                uint4 v = *(const uint4*)(xfr + (t * 4 + kk) * 1024);
                af[t][0] = v.x; af[t][1] = v.y; af[t][2] = v.z; af[t][3] = v.w;
            }
            #pragma unroll
            for (int nt = 0; nt < 2; nt++) {
                const int ntA = qt * 2 + nt;
                uint2 av = __ldg((const uint2*)(g_w1h + ((kk * 16 + ntA) * 32 + lane) * 2));
                #pragma unroll
                for (int t = 0; t < 3; t++) mma16h(accA[t][nt], af[t], av.x, av.y);
                const int ntC = 8 + qt * 2 + nt;
                uint2 cv = __ldg((const uint2*)(g_w1h + ((kk * 16 + ntC) * 32 + lane) * 2));
                #pragma unroll
                for (int t = 0; t < 3; t++) mma16h(accC[t][nt], af[t], cv.x, cv.y);
            }
        }
        // half2 gating
        __half2 sph[6][2];
        #pragma unroll
        for (int q = 0; q < 6; q++)
            #pragma unroll
            for (int r = 0; r < 2; r++) sph[q][r] = __float2half2_rn(0.f);

        #pragma unroll
        for (int nt = 0; nt < 2; nt++) {
            const uint32_t w2u = w2h[qt * 8 + nt * 4 + tig];
            const __half2 wv = *reinterpret_cast<const __half2*>(&w2u);
            #pragma unroll
            for (int r = 0; r < 2; r++) {
                __half2 A0 = *reinterpret_cast<__half2*>(&accA[0][nt][r]);
                __half2 A1 = *reinterpret_cast<__half2*>(&accA[1][nt][r]);
                __half2 A2 = *reinterpret_cast<__half2*>(&accA[2][nt][r]);
                __half2 C0 = *reinterpret_cast<__half2*>(&accC[0][nt][r]);
                __half2 C1 = *reinterpret_cast<__half2*>(&accC[1][nt][r]);
                __half2 C2 = *reinterpret_cast<__half2*>(&accC[2][nt][r]);
                sph[0][r] = gelu_w2_h2(__hadd2(A0, C1), wv, sph[0][r]);
                sph[1][r] = gelu_w2_h2(__hadd2(A0, C2), wv, sph[1][r]);
                sph[2][r] = gelu_w2_h2(__hadd2(A1, C0), wv, sph[2][r]);
                sph[3][r] = gelu_w2_h2(__hadd2(A1, C2), wv, sph[3][r]);
                sph[4][r] = gelu_w2_h2(__hadd2(A2, C0), wv, sph[4][r]);
                sph[5][r] = gelu_w2_h2(__hadd2(A2, C1), wv, sph[5][r]);
            }
        }
        #pragma unroll
        for (int q = 0; q < 6; q++)
            #pragma unroll
            for (int r = 0; r < 2; r++) {
                float2 f = __half22float2(sph[q][r]);
                spf[q][r] += f.x + f.y;
            }
    }
    // width-4 butterfly reduce + in-register sigmoid -> gate half2 broadcasts
    __half2 mh[2][6];   // [row][pair]
    {
        const float b2v = __ldg(b2);
        #pragma unroll
        for (int q = 0; q < 6; q++) {
            #pragma unroll
            for (int r = 0; r < 2; r++) {
                float v = spf[q][r];
                v += __shfl_xor_sync(0xffffffffu, v, 1, 4);
                v += __shfl_xor_sync(0xffffffffu, v, 2, 4);
                mh[r][q] = __float2half2_rn(sigmoid_t(v + b2v));
            }
        }
    }

    // -------- GEMM2 (fp16 MMA, fp32 acc): full k, full n per warp --------
    float D[8][4];
    #pragma unroll
    for (int n = 0; n < 8; n++)
        #pragma unroll
        for (int r = 0; r < 4; r++) D[n][r] = 0.f;

    #pragma unroll
    for (int dd = 0; dd < 4; dd++) {
        __half2 xf[3][4];
        #pragma unroll
        for (int t = 0; t < 3; t++) {
            uint4 v = *(const uint4*)(xfr + (t * 4 + dd) * 1024);
            xf[t][0] = *reinterpret_cast<__half2*>(&v.x);
            xf[t][1] = *reinterpret_cast<__half2*>(&v.y);
            xf[t][2] = *reinterpret_cast<__half2*>(&v.z);
            xf[t][3] = *reinterpret_cast<__half2*>(&v.w);
        }
        uint32_t yfa[3][4];
        #pragma unroll
        for (int t = 0; t < 3; t++) {
            const int u1 = (t == 0) ? 1 : 0;
            const int u2 = (t == 2) ? 1 : 2;
            #pragma unroll
            for (int r = 0; r < 4; r++) {
                const int row = r & 1;
                __half2 y = __hfma2(mh[row][2 * t + 1], xf[u2][r],
                            __hfma2(mh[row][2 * t],     xf[u1][r], xf[t][r]));
                yfa[t][r] = *reinterpret_cast<uint32_t*>(&y);
            }
        }
        #pragma unroll
        for (int t = 0; t < 3; t++) {
            const int kc = t * 4 + dd;
            #pragma unroll
            for (int n = 0; n < 8; n++) {
                uint2 bv = __ldg((const uint2*)(g_wfh + ((kc * 8 + n) * 32 + lane) * 2));
                mma16(D[n], yfa[t], bv.x, bv.y);
            }
        }
    }
    __syncthreads();   // all xh reads done; safe to overlay stg

    // -------- stage D into [64][132] for coalesced output --------
    #pragma unroll
    for (int n = 0; n < 8; n++) {
        #pragma unroll
        for (int cc = 0; cc < 2; cc++) {
            const int col = n * 8 + 2 * tig + cc;
            stg[col * 132 + m0 + g]     = D[n][cc];
            stg[col * 132 + m0 + g + 8] = D[n][2 + cc];
        }
    }
    __syncthreads();

    // -------- epilogue: stg + bf -> gmem (float4) --------
    {
        float* op = out + (size_t)bb * 64 * 65536 + hw0;
        #pragma unroll
        for (int i = tid; i < 64 * 32; i += THREADS) {
            int o = i >> 5, p4 = (i & 31) << 2;
            float4 v = *(const float4*)(stg + o * 132 + p4);
            const float bfv = bfs[o];
            v.x += bfv; v.y += bfv; v.z += bfv; v.w += bfv;
            *(float4*)(op + (size_t)o * 65536 + p4) = v;
        }
    }
}

extern "C" void kernel_launch(void* const* d_in, const int* in_sizes, int n_in,
                              void* d_out, int out_size)
{
    const float* deg = (const float*)d_in[0];
    const float* W1  = (const float*)d_in[1];
    const float* b1  = (const float*)d_in[2];
    const float* W2  = (const float*)d_in[3];
    const float* b2  = (const float*)d_in[4];
    const float* Wf  = (const float*)d_in[5];
    const float* bf  = (const float*)d_in[6];
    float* outp = (float*)d_out;

    prep_w<<<20, 512>>>(W1, Wf);
    cudaFuncSetAttribute(dig_mma14, cudaFuncAttributeMaxDynamicSharedMemorySize, SM_BYTES);
    dig_mma14<<<NBLOCKS, THREADS, SM_BYTES>>>(deg, b1, W2, b2, bf, outp);
}